// round 10
// baseline (speedup 1.0000x reference)
#include <cuda_runtime.h>
#include <cuda_bf16.h>

// Nearest-codeword quantization, uniform sorted 16-entry codebook.
// out[i] = argmin_c |x[i] - c|, tie toward the LOWER codeword.
//
// R10 = R8 (no reg cap; occ ~60% was FINE) with ILP=8 front-batched float4
// loads. R9 showed the binding resource is outstanding-loads-per-SM =
// warps x per-warp-MLP; capping regs raised occupancy but serialized loads
// (DRAM fell). So push the MLP axis instead: 8 independent LDG.128 issued
// back-to-back per thread.
//
// Hot path per element (branchless): t = fma(x,inv,b0); tc = clamp(t,0,15);
// tr = rintf(tc); val = fma(tr,step,c0); maxd = fmax(maxd,|tc-tr|).
// ONE __any_sync vote per float4 routes the warp to an exact recompute
// (true codebook via __ldg, reference tie-break) when any lane is within
// EPS=1e-4 (index space) of a midpoint. val is <=1 ulp from the stored
// linspace codeword (rel_err ~7e-8, tol 1e-3).

#define K_CB 16
#define ILP  8

__global__ void __launch_bounds__(256)
quant_uniform_kernel(const float4* __restrict__ x,
                     const float*  __restrict__ cb,
                     float4* __restrict__ out,
                     int n4)
{
    const float c0 = __ldg(cb);
    const float cK = __ldg(cb + K_CB - 1);
    const float step     = (cK - c0) * (1.0f / (float)(K_CB - 1));
    const float inv_step = (float)(K_CB - 1) / (cK - c0);
    const float b0 = -c0 * inv_step;
    const float TH = 0.5f - 1e-4f;      // guard threshold in index space

    const int tid  = threadIdx.x;
    const int bdim = blockDim.x;                  // 256
    const int base = blockIdx.x * (bdim * ILP) + tid;

    if (base + (ILP - 1) * bdim < n4) {
        // ILP fully-coalesced independent LDG.128, front-batched.
        float4 vv[ILP];
#pragma unroll
        for (int u = 0; u < ILP; u++)
            vv[u] = x[base + u * bdim];

#pragma unroll
        for (int u = 0; u < ILP; u++) {
            float4 r;
            const float* vp = reinterpret_cast<const float*>(&vv[u]);
            float* rp = reinterpret_cast<float*>(&r);

            float maxd = 0.0f;
#pragma unroll
            for (int j = 0; j < 4; j++) {
                float xv = vp[j];
                float t  = fmaf(xv, inv_step, b0);
                float tc = fminf(fmaxf(t, 0.0f), (float)(K_CB - 1));
                float tr = rintf(tc);
                rp[j] = fmaf(tr, step, c0);
                maxd = fmaxf(maxd, fabsf(tc - tr));   // FMNMX with |.|
            }

            // One vote per float4: does ANY lane need the exact path?
            if (__any_sync(0xFFFFFFFFu, maxd >= TH)) {
#pragma unroll
                for (int j = 0; j < 4; j++) {
                    float xv = vp[j];
                    float t  = fmaf(xv, inv_step, b0);
                    int k = min(max(__float2int_rd(t), 0), K_CB - 2);
                    float lo = __ldg(cb + k);
                    float hi = __ldg(cb + k + 1);
                    rp[j] = (fabsf(xv - lo) <= fabsf(xv - hi)) ? lo : hi;
                }
            }

            out[base + u * bdim] = r;
        }
    } else {
        // Tail (not taken for 8192x8192): always-exact scalar path.
        for (int u = 0; u < ILP; u++) {
            int idx = base + u * bdim;
            if (idx >= n4) break;
            float4 v = x[idx];
            float4 r;
            const float* vp = reinterpret_cast<const float*>(&v);
            float* rp = reinterpret_cast<float*>(&r);
#pragma unroll
            for (int j = 0; j < 4; j++) {
                float xv = vp[j];
                float t  = fmaf(xv, inv_step, b0);
                int k = min(max(__float2int_rd(t), 0), K_CB - 2);
                float lo = __ldg(cb + k);
                float hi = __ldg(cb + k + 1);
                rp[j] = (fabsf(xv - lo) <= fabsf(xv - hi)) ? lo : hi;
            }
            out[idx] = r;
        }
    }
}

extern "C" void kernel_launch(void* const* d_in, const int* in_sizes, int n_in,
                              void* d_out, int out_size)
{
    const float* x  = (const float*)d_in[0];
    const float* cb = (const float*)d_in[1];
    float* out = (float*)d_out;

    int n  = in_sizes[0];         // 8192*8192 = 67,108,864
    int n4 = n >> 2;              // 16,777,216 float4

    const int threads = 256;
    const int per_block = threads * ILP;               // 2048 float4 / block
    int blocks = (n4 + per_block - 1) / per_block;     // 8192

    quant_uniform_kernel<<<blocks, threads>>>(
        (const float4*)x, cb, (float4*)out, n4);
}

// round 11
// speedup vs baseline: 1.0070x; 1.0070x over previous
#include <cuda_runtime.h>
#include <cuda_bf16.h>

// Nearest-codeword quantization, uniform sorted 16-entry codebook.
// out[i] = argmin_c |x[i] - c|, tie toward the LOWER codeword.
//
// R11 = R8 (best: 82.0us, DRAM 80.6%) + streaming cache hints (.cs) on the
// bulk loads/stores. R8 vs R10 showed outstanding-load scaling is saturated
// (~6.3-6.4 TB/s for both); the remaining lever is L2 eviction policy for
// the two non-reused streams.
//
// Hot path per element (branchless): t = fma(x,inv,b0); tc = clamp(t,0,15);
// tr = rintf(tc); val = fma(tr,step,c0); maxd = fmax(maxd,|tc-tr|).
// ONE __any_sync vote per float4 routes the warp to an exact recompute
// (true codebook via __ldg, reference tie-break) when any lane is within
// EPS=1e-4 (index space) of a midpoint (~2.5% of warp-iterations).
// val is <=1 ulp from the stored linspace codeword (rel_err ~7e-8, tol 1e-3).

#define K_CB 16

__global__ void __launch_bounds__(256)
quant_uniform_kernel(const float4* __restrict__ x,
                     const float*  __restrict__ cb,
                     float4* __restrict__ out,
                     int n4)
{
    const float c0 = __ldg(cb);
    const float cK = __ldg(cb + K_CB - 1);
    const float step     = (cK - c0) * (1.0f / (float)(K_CB - 1));
    const float inv_step = (float)(K_CB - 1) / (cK - c0);
    const float b0 = -c0 * inv_step;
    const float TH = 0.5f - 1e-4f;      // guard threshold in index space

    const int tid  = threadIdx.x;
    const int bdim = blockDim.x;                  // 256
    const int base = blockIdx.x * (bdim * 4) + tid;

    if (base + 3 * bdim < n4) {
        // 4 fully-coalesced independent LDG.128.CS, front-batched.
        float4 vv[4];
        vv[0] = __ldcs(x + base + 0 * bdim);
        vv[1] = __ldcs(x + base + 1 * bdim);
        vv[2] = __ldcs(x + base + 2 * bdim);
        vv[3] = __ldcs(x + base + 3 * bdim);

#pragma unroll
        for (int u = 0; u < 4; u++) {
            float4 r;
            const float* vp = reinterpret_cast<const float*>(&vv[u]);
            float* rp = reinterpret_cast<float*>(&r);

            float maxd = 0.0f;
#pragma unroll
            for (int j = 0; j < 4; j++) {
                float xv = vp[j];
                float t  = fmaf(xv, inv_step, b0);
                float tc = fminf(fmaxf(t, 0.0f), (float)(K_CB - 1));
                float tr = rintf(tc);
                rp[j] = fmaf(tr, step, c0);
                maxd = fmaxf(maxd, fabsf(tc - tr));   // FMNMX with |.|
            }

            // One vote per float4: does ANY lane need the exact path?
            if (__any_sync(0xFFFFFFFFu, maxd >= TH)) {
#pragma unroll
                for (int j = 0; j < 4; j++) {
                    float xv = vp[j];
                    float t  = fmaf(xv, inv_step, b0);
                    int k = min(max(__float2int_rd(t), 0), K_CB - 2);
                    float lo = __ldg(cb + k);
                    float hi = __ldg(cb + k + 1);
                    rp[j] = (fabsf(xv - lo) <= fabsf(xv - hi)) ? lo : hi;
                }
            }

            __stcs(out + base + u * bdim, r);
        }
    } else {
        // Tail (not taken for 8192x8192): always-exact scalar path.
        for (int u = 0; u < 4; u++) {
            int idx = base + u * bdim;
            if (idx >= n4) break;
            float4 v = x[idx];
            float4 r;
            const float* vp = reinterpret_cast<const float*>(&v);
            float* rp = reinterpret_cast<float*>(&r);
#pragma unroll
            for (int j = 0; j < 4; j++) {
                float xv = vp[j];
                float t  = fmaf(xv, inv_step, b0);
                int k = min(max(__float2int_rd(t), 0), K_CB - 2);
                float lo = __ldg(cb + k);
                float hi = __ldg(cb + k + 1);
                rp[j] = (fabsf(xv - lo) <= fabsf(xv - hi)) ? lo : hi;
            }
            out[idx] = r;
        }
    }
}

extern "C" void kernel_launch(void* const* d_in, const int* in_sizes, int n_in,
                              void* d_out, int out_size)
{
    const float* x  = (const float*)d_in[0];
    const float* cb = (const float*)d_in[1];
    float* out = (float*)d_out;

    int n  = in_sizes[0];         // 8192*8192 = 67,108,864
    int n4 = n >> 2;              // 16,777,216 float4

    const int threads = 256;
    const int per_block = threads * 4;                 // 1024 float4 / block
    int blocks = (n4 + per_block - 1) / per_block;     // 16384

    quant_uniform_kernel<<<blocks, threads>>>(
        (const float4*)x, cb, (float4*)out, n4);
}